// round 3
// baseline (speedup 1.0000x reference)
#include <cuda_runtime.h>
#include <math.h>

// Problem constants
#define BSZ   64
#define TT    256
#define IND   64
#define HD    768
#define G4    3072      // 4*H
#define NCTA  128       // persistent grid size (<= 148 SMs -> all co-resident)
#define LUD   256

// Scratch (static device allocations are the sanctioned workaround)
__device__ __align__(16) float g_XG[(size_t)TT * G4 * BSZ];   // [t][gatecol][b]  (layer0, then reused for layer1)
__device__ __align__(16) float g_H1[(size_t)TT * HD * BSZ];   // [t][k>>2][b][k&3]
__device__ __align__(16) float g_H2[2 * HD * BSZ];            // double buffer, same interleave
__device__ unsigned long long g_bar = 0;                      // cumulative barrier counter

// ---------------------------------------------------------------------------
// Software grid barrier: cumulative-ticket scheme, safe across graph replays.
// ---------------------------------------------------------------------------
__device__ __forceinline__ void grid_barrier()
{
    __threadfence();          // release h stores
    __syncthreads();
    if (threadIdx.x == 0) {
        unsigned long long ticket = atomicAdd(&g_bar, 1ULL) + 1ULL;
        unsigned long long need = ((ticket + (NCTA - 1)) / NCTA) * NCTA;
        volatile unsigned long long* p = &g_bar;
        while (*p < need) { __nanosleep(40); }
    }
    __syncthreads();
    __threadfence();          // acquire
}

__device__ __forceinline__ float sigmoidf_(float x)
{
    return 1.0f / (1.0f + __expf(-x));
}

// ---------------------------------------------------------------------------
// proj0: g_XG[t][c][b] = sum_d (x[b][t][d]/1.5) * Wih0[c][d] + bih0[c] + bhh0[c]
// ---------------------------------------------------------------------------
__global__ void proj0_kernel(const float* __restrict__ x,
                             const float* __restrict__ Wih0,
                             const float* __restrict__ bih0,
                             const float* __restrict__ bhh0)
{
    __shared__ float4 Xs4[64 * 17];
    __shared__ float4 Ws4[64 * 17];
    float* Xs = (float*)Xs4;
    float* Ws = (float*)Ws4;

    const int t   = blockIdx.y;
    const int c0  = blockIdx.x * 64;
    const int tid = threadIdx.x;
    const float inv = 1.0f / 1.5f;

    for (int idx = tid; idx < 64 * 64; idx += 256) {
        int b = idx >> 6, d = idx & 63;
        Xs[b * 68 + d] = x[((b * TT) + t) * IND + d] * inv;
    }
    for (int idx = tid; idx < 64 * 64; idx += 256) {
        int c = idx >> 6, d = idx & 63;
        Ws[c * 68 + d] = Wih0[(c0 + c) * IND + d];
    }
    __syncthreads();

    const int b  = tid & 63;
    const int cw = tid >> 6;

    float acc[16];
#pragma unroll
    for (int m = 0; m < 16; m++) acc[m] = 0.0f;

#pragma unroll
    for (int d4 = 0; d4 < 16; d4++) {
        float4 xv = Xs4[b * 17 + d4];
#pragma unroll
        for (int m = 0; m < 16; m++) {
            float4 wv = Ws4[(cw + 4 * m) * 17 + d4];
            acc[m] += xv.x * wv.x + xv.y * wv.y + xv.z * wv.z + xv.w * wv.w;
        }
    }
#pragma unroll
    for (int m = 0; m < 16; m++) {
        int c = c0 + cw + 4 * m;
        g_XG[((size_t)t * G4 + c) * 64 + b] = acc[m] + bih0[c] + bhh0[c];
    }
}

// ---------------------------------------------------------------------------
// proj1: layer-1 input projection, parallel over all (t, c):
//   g_XG[t][c][b] = sum_k H1[t][k][b] * Wih1[c][k] + bih1[c] + bhh1[c]
// K=768, chunked by 64. H1 is [t][k4][b][4] interleaved (float4 over k).
// ---------------------------------------------------------------------------
__global__ void proj1_kernel(const float* __restrict__ Wih1,
                             const float* __restrict__ bih1,
                             const float* __restrict__ bhh1)
{
    __shared__ float4 Hs4[64 * 17];   // [b][k4]
    __shared__ float4 Ws4[64 * 17];   // [c][k4]

    const int t   = blockIdx.y;
    const int c0  = blockIdx.x * 64;
    const int tid = threadIdx.x;
    const int b   = tid & 63;
    const int cw  = tid >> 6;

    const float4* h4 = (const float4*)g_H1 + (size_t)t * (HD * 16); // 12288 f4/t

    float acc[16];
#pragma unroll
    for (int m = 0; m < 16; m++) acc[m] = 0.0f;

    for (int k0 = 0; k0 < 12; k0++) {       // 12 chunks of 64 k
        __syncthreads();
        for (int idx = tid; idx < 1024; idx += 256) {
            int bb = idx & 63, k4i = idx >> 6;
            Hs4[bb * 17 + k4i] = h4[(k0 * 16 + k4i) * 64 + bb];   // coalesced over bb
        }
        for (int idx = tid; idx < 1024; idx += 256) {
            int cc = idx >> 4, kc4 = idx & 15;
            Ws4[cc * 17 + kc4] =
                *(const float4*)(Wih1 + (size_t)(c0 + cc) * HD + k0 * 64 + kc4 * 4);
        }
        __syncthreads();
#pragma unroll
        for (int d4 = 0; d4 < 16; d4++) {
            float4 xv = Hs4[b * 17 + d4];
#pragma unroll
            for (int m = 0; m < 16; m++) {
                float4 wv = Ws4[(cw + 4 * m) * 17 + d4];
                acc[m] += xv.x * wv.x + xv.y * wv.y + xv.z * wv.z + xv.w * wv.w;
            }
        }
    }
#pragma unroll
    for (int m = 0; m < 16; m++) {
        int c = c0 + cw + 4 * m;
        g_XG[((size_t)t * G4 + c) * 64 + b] = acc[m] + bih1[c] + bhh1[c];
    }
}

// ---------------------------------------------------------------------------
// Recurrence kernel body (shared by both layers):
// CTA owns 6 h-cols; per step, stage h[t-1] into smem (2 chunks of 384 k),
// then FFMA against weights held in smem. h exchanged via L2 + grid barrier.
// ---------------------------------------------------------------------------
__global__ void __launch_bounds__(384, 1)
lstm0_kernel(const float* __restrict__ Whh0)
{
    extern __shared__ float4 sm[];
    float4* Wsh = sm;            // 4608 f4 (73728 B): [k][jj][gate]
    float4* Hs  = sm + 4608;     // 6144 f4 (98304 B): [k4][b]
    float*  Wsf = (float*)Wsh;

    const int tid = threadIdx.x;
    const int jl  = tid / 64;
    const int b   = tid & 63;
    const int j   = blockIdx.x * 6 + jl;

    for (int idx = tid; idx < 768 * 24; idx += 384) {
        int k  = idx / 24;
        int r  = idx % 24;
        int jj = r >> 2;
        int gi = r & 3;
        Wsf[idx] = Whh0[(gi * 768 + blockIdx.x * 6 + jj) * 768 + k];
    }
    __syncthreads();

    float c = 0.0f;
    for (int t = 0; t < TT; t++) {
        int base = (t * G4 + j) * 64 + b;
        float ai = g_XG[base];
        float af = g_XG[base + 768 * 64];
        float ag = g_XG[base + 1536 * 64];
        float ao = g_XG[base + 2304 * 64];

        if (t > 0) {
            const float4* h4 = (const float4*)g_H1 + (size_t)(t - 1) * (HD * 16);
#pragma unroll
            for (int ch = 0; ch < 2; ch++) {
                __syncthreads();
#pragma unroll
                for (int i = 0; i < 16; i++) {
                    int idx = tid + i * 384;
                    Hs[idx] = __ldcg(&h4[ch * 6144 + idx]);
                }
                __syncthreads();
#pragma unroll 8
                for (int k4 = 0; k4 < 96; k4++) {
                    float4 hv = Hs[k4 * 64 + b];
                    int wb = ((ch * 96 + k4) * 4) * 6 + jl;
                    float4 w0 = Wsh[wb];
                    float4 w1 = Wsh[wb + 6];
                    float4 w2 = Wsh[wb + 12];
                    float4 w3 = Wsh[wb + 18];
                    ai += hv.x * w0.x + hv.y * w1.x + hv.z * w2.x + hv.w * w3.x;
                    af += hv.x * w0.y + hv.y * w1.y + hv.z * w2.y + hv.w * w3.y;
                    ag += hv.x * w0.z + hv.y * w1.z + hv.z * w2.z + hv.w * w3.z;
                    ao += hv.x * w0.w + hv.y * w1.w + hv.z * w2.w + hv.w * w3.w;
                }
            }
        }
        float ig = sigmoidf_(ai);
        float fg = sigmoidf_(af);
        float gg = tanhf(ag);
        float og = sigmoidf_(ao);
        c = fg * c + ig * gg;
        float h = og * tanhf(c);

        g_H1[(size_t)t * (HD * 64) + (size_t)(((j >> 2) * 64 + b) * 4 + (j & 3))] = h;
        grid_barrier();
    }
}

__global__ void __launch_bounds__(384, 1)
lstm1_kernel(const float* __restrict__ Whh1)
{
    extern __shared__ float4 sm[];
    float4* Wsh = sm;
    float4* Hs  = sm + 4608;
    float*  Wsf = (float*)Wsh;

    const int tid = threadIdx.x;
    const int jl  = tid / 64;
    const int b   = tid & 63;
    const int j   = blockIdx.x * 6 + jl;

    for (int idx = tid; idx < 768 * 24; idx += 384) {
        int k  = idx / 24;
        int r  = idx % 24;
        int jj = r >> 2;
        int gi = r & 3;
        Wsf[idx] = Whh1[(gi * 768 + blockIdx.x * 6 + jj) * 768 + k];
    }
    __syncthreads();

    float c = 0.0f;
    for (int t = 0; t < TT; t++) {
        int base = (t * G4 + j) * 64 + b;
        float ai = g_XG[base];
        float af = g_XG[base + 768 * 64];
        float ag = g_XG[base + 1536 * 64];
        float ao = g_XG[base + 2304 * 64];

        if (t > 0) {
            const float4* h4 = (const float4*)g_H2 + (size_t)((t - 1) & 1) * (HD * 16);
#pragma unroll
            for (int ch = 0; ch < 2; ch++) {
                __syncthreads();
#pragma unroll
                for (int i = 0; i < 16; i++) {
                    int idx = tid + i * 384;
                    Hs[idx] = __ldcg(&h4[ch * 6144 + idx]);
                }
                __syncthreads();
#pragma unroll 8
                for (int k4 = 0; k4 < 96; k4++) {
                    float4 hv = Hs[k4 * 64 + b];
                    int wb = ((ch * 96 + k4) * 4) * 6 + jl;
                    float4 w0 = Wsh[wb];
                    float4 w1 = Wsh[wb + 6];
                    float4 w2 = Wsh[wb + 12];
                    float4 w3 = Wsh[wb + 18];
                    ai += hv.x * w0.x + hv.y * w1.x + hv.z * w2.x + hv.w * w3.x;
                    af += hv.x * w0.y + hv.y * w1.y + hv.z * w2.y + hv.w * w3.y;
                    ag += hv.x * w0.z + hv.y * w1.z + hv.z * w2.z + hv.w * w3.z;
                    ao += hv.x * w0.w + hv.y * w1.w + hv.z * w2.w + hv.w * w3.w;
                }
            }
        }
        float ig = sigmoidf_(ai);
        float fg = sigmoidf_(af);
        float gg = tanhf(ag);
        float og = sigmoidf_(ao);
        c = fg * c + ig * gg;
        float h = og * tanhf(c);

        g_H2[(size_t)(t & 1) * (HD * 64) + (size_t)(((j >> 2) * 64 + b) * 4 + (j & 3))] = h;
        grid_barrier();
    }
}

// ---------------------------------------------------------------------------
// fc head
// ---------------------------------------------------------------------------
__global__ void fc_kernel(const float* __restrict__ W1, const float* __restrict__ b1,
                          const float* __restrict__ W2, const float* __restrict__ b2,
                          float* __restrict__ out)
{
    const int b = blockIdx.x;
    const int l = threadIdx.x;

    const float4* h2p = (const float4*)(g_H2 + (size_t)1 * (HD * 64));  // t=255 -> parity 1
    const float4* w1p = (const float4*)(W1 + (size_t)l * HD);

    float acc = 0.0f;
#pragma unroll 4
    for (int k4 = 0; k4 < 192; k4++) {
        float4 hv = h2p[k4 * 64 + b];
        float4 wv = w1p[k4];
        acc += hv.x * wv.x + hv.y * wv.y + hv.z * wv.z + hv.w * wv.w;
    }
    float z = acc + b1[l];
    float s = z / (1.0f + fabsf(z));
    float p = s * W2[l];

    __shared__ float red[LUD];
    red[l] = p;
    __syncthreads();
    for (int off = LUD / 2; off > 0; off >>= 1) {
        if (l < off) red[l] += red[l + off];
        __syncthreads();
    }
    if (l == 0) out[b] = (red[0] + b2[0]) * 70.0f;
}

// ---------------------------------------------------------------------------
extern "C" void kernel_launch(void* const* d_in, const int* in_sizes, int n_in,
                              void* d_out, int out_size)
{
    const float* x    = (const float*)d_in[0];
    const float* Wih0 = (const float*)d_in[1];
    const float* Whh0 = (const float*)d_in[2];
    const float* bih0 = (const float*)d_in[3];
    const float* bhh0 = (const float*)d_in[4];
    const float* Wih1 = (const float*)d_in[5];
    const float* Whh1 = (const float*)d_in[6];
    const float* bih1 = (const float*)d_in[7];
    const float* bhh1 = (const float*)d_in[8];
    const float* W1   = (const float*)d_in[9];
    const float* b1   = (const float*)d_in[10];
    const float* W2   = (const float*)d_in[11];
    const float* b2   = (const float*)d_in[12];
    float* out = (float*)d_out;

    const int lstm_smem = (4608 + 6144) * 16;   // 172032 B
    cudaFuncSetAttribute(lstm0_kernel, cudaFuncAttributeMaxDynamicSharedMemorySize, lstm_smem);
    cudaFuncSetAttribute(lstm1_kernel, cudaFuncAttributeMaxDynamicSharedMemorySize, lstm_smem);

    proj0_kernel<<<dim3(48, 256), 256>>>(x, Wih0, bih0, bhh0);
    lstm0_kernel<<<NCTA, 384, lstm_smem>>>(Whh0);
    proj1_kernel<<<dim3(48, 256), 256>>>(Wih1, bih1, bhh1);
    lstm1_kernel<<<NCTA, 384, lstm_smem>>>(Whh1);
    fc_kernel<<<BSZ, LUD>>>(W1, b1, W2, b2, out);
}

// round 4
// speedup vs baseline: 3.0779x; 3.0779x over previous
#include <cuda_runtime.h>
#include <cuda_bf16.h>
#include <math.h>

#define BSZ   64
#define TT    256
#define IND   64
#define HD    768
#define G4    3072
#define NB    48          // persistent lstm grid: CTA nb owns h-cols j0=nb*16..+15
#define LUD   256
#define STEP_WORDS 24576  // A-frag buffer per step: 48kt*4mt*32lane*4words (98304 B)

// Scratch (static device arrays are the sanctioned workaround)
__device__ __align__(16) float    g_XG[(size_t)TT * G4 * BSZ];     // [t][c][b] fp32 gate preacts
__device__ __align__(16) unsigned g_H1f[(size_t)TT * STEP_WORDS];  // h1 bf16 frags, all t
__device__ __align__(16) unsigned g_H2f[2 * STEP_WORDS];           // h2 bf16 frags, parity
__device__ __align__(16) float    g_h2pl[BSZ * HD];                // planar fp32 h2 (last step)
__device__ unsigned long long g_bar = 0;

// ---------------------------------------------------------------------------
__device__ __forceinline__ void grid_barrier()
{
    __threadfence();
    __syncthreads();
    if (threadIdx.x == 0) {
        unsigned long long ticket = atomicAdd(&g_bar, 1ULL) + 1ULL;
        unsigned long long need = ((ticket + (NB - 1)) / NB) * NB;
        volatile unsigned long long* p = &g_bar;
        while (*p < need) { __nanosleep(20); }
    }
    __syncthreads();
    __threadfence();
}

__device__ __forceinline__ float sigmoidf_(float x) { return 1.0f / (1.0f + __expf(-x)); }

__device__ __forceinline__ unsigned packbf(float lo, float hi)
{
    __nv_bfloat162 v = __floats2bfloat162_rn(lo, hi);
    return *reinterpret_cast<unsigned*>(&v);
}

__device__ __forceinline__ void mma16816(float* acc, uint4 a, uint2 b)
{
    asm volatile(
        "mma.sync.aligned.m16n8k16.row.col.f32.bf16.bf16.f32 "
        "{%0,%1,%2,%3}, {%4,%5,%6,%7}, {%8,%9}, {%0,%1,%2,%3};"
        : "+f"(acc[0]), "+f"(acc[1]), "+f"(acc[2]), "+f"(acc[3])
        : "r"(a.x), "r"(a.y), "r"(a.z), "r"(a.w), "r"(b.x), "r"(b.y));
}

// Stage a 64(gatecol) x 768(k) weight slice into smem as bf16 B-fragments.
// n = gate*16 + jj -> weight row gate*768 + j0 + jj. Frag layout per
// mma.m16n8k16 .col B: lane holds k={tig*2,+1} (word0) and {tig*2+8,+9} (word1), n=gp.
__device__ __forceinline__ void stage_B(const float* __restrict__ W, int j0,
                                        __nv_bfloat16* Bsh, int tid)
{
    for (int idx = tid; idx < 64 * 768; idx += 256) {
        int n = idx / 768, k = idx - n * 768;
        int gate = n >> 4, jj = n & 15;
        float w = W[(size_t)(gate * 768 + j0 + jj) * 768 + k];
        int kt = k >> 4, kr = k & 15, nt = n >> 3, nn = n & 7;
        int lane = nn * 4 + ((kr & 7) >> 1);
        int word = kr >> 3, half = kr & 1;
        Bsh[(((kt * 8 + nt) * 32 + lane) * 2 + word) * 2 + half] = __float2bfloat16(w);
    }
}

// Warp-level GEMM mainloop: acc over 24 k-tiles (ki half), dump to Cs.
// As: A-frags in global (uint4 per lane per (kt,mt)). Bs: smem frag words.
__device__ __forceinline__ void gemm_accum_dump(
    const uint4* __restrict__ As, const unsigned* __restrict__ Bs,
    float* __restrict__ Cs, int lane, int ki, int mi, int ni)
{
    float acc[2][4][4] = {};
    uint4 abuf[2][12];
#pragma unroll
    for (int kk = 0; kk < 6; kk++) {
        int kt = ki * 24 + kk;
        abuf[0][kk * 2 + 0] = __ldcg(As + (kt * 4 + mi * 2 + 0) * 32 + lane);
        abuf[0][kk * 2 + 1] = __ldcg(As + (kt * 4 + mi * 2 + 1) * 32 + lane);
    }
#pragma unroll
    for (int ch = 0; ch < 4; ch++) {
        if (ch < 3) {
#pragma unroll
            for (int kk = 0; kk < 6; kk++) {
                int kt = ki * 24 + (ch + 1) * 6 + kk;
                abuf[(ch + 1) & 1][kk * 2 + 0] = __ldcg(As + (kt * 4 + mi * 2 + 0) * 32 + lane);
                abuf[(ch + 1) & 1][kk * 2 + 1] = __ldcg(As + (kt * 4 + mi * 2 + 1) * 32 + lane);
            }
        }
#pragma unroll
        for (int kk = 0; kk < 6; kk++) {
            int kt = ki * 24 + ch * 6 + kk;
            uint4 a0 = abuf[ch & 1][kk * 2 + 0];
            uint4 a1 = abuf[ch & 1][kk * 2 + 1];
#pragma unroll
            for (int bn = 0; bn < 4; bn++) {
                int nt = ni * 4 + bn;
                uint2 bb = *(const uint2*)(Bs + ((kt * 8 + nt) * 32 + lane) * 2);
                mma16816(acc[0][bn], a0, bb);
                mma16816(acc[1][bn], a1, bb);
            }
        }
    }
    int gp = lane >> 2, tig = lane & 3;
#pragma unroll
    for (int am = 0; am < 2; am++)
#pragma unroll
        for (int bn = 0; bn < 4; bn++) {
            int row = mi * 32 + am * 16 + gp;
            int col = ni * 32 + bn * 8 + tig * 2;
            float* cp = Cs + (ki * 64 + row) * 65 + col;
            cp[0] = acc[am][bn][0];
            cp[1] = acc[am][bn][1];
            cp[8 * 65 + 0] = acc[am][bn][2];
            cp[8 * 65 + 1] = acc[am][bn][3];
        }
}

// ---------------------------------------------------------------------------
// proj0 (fp32 precision anchor): g_XG[t][c][b] = (x/1.5)*Wih0^T + bih0 + bhh0
// ---------------------------------------------------------------------------
__global__ void proj0_kernel(const float* __restrict__ x,
                             const float* __restrict__ Wih0,
                             const float* __restrict__ bih0,
                             const float* __restrict__ bhh0)
{
    __shared__ float4 Xs4[64 * 17];
    __shared__ float4 Ws4[64 * 17];
    float* Xs = (float*)Xs4;
    float* Ws = (float*)Ws4;

    const int t   = blockIdx.y;
    const int c0  = blockIdx.x * 64;
    const int tid = threadIdx.x;
    const float inv = 1.0f / 1.5f;

    for (int idx = tid; idx < 64 * 64; idx += 256) {
        int b = idx >> 6, d = idx & 63;
        Xs[b * 68 + d] = x[((b * TT) + t) * IND + d] * inv;
    }
    for (int idx = tid; idx < 64 * 64; idx += 256) {
        int c = idx >> 6, d = idx & 63;
        Ws[c * 68 + d] = Wih0[(c0 + c) * IND + d];
    }
    __syncthreads();

    const int b  = tid & 63;
    const int cw = tid >> 6;

    float acc[16];
#pragma unroll
    for (int m = 0; m < 16; m++) acc[m] = 0.0f;
#pragma unroll
    for (int d4 = 0; d4 < 16; d4++) {
        float4 xv = Xs4[b * 17 + d4];
#pragma unroll
        for (int m = 0; m < 16; m++) {
            float4 wv = Ws4[(cw + 4 * m) * 17 + d4];
            acc[m] += xv.x * wv.x + xv.y * wv.y + xv.z * wv.z + xv.w * wv.w;
        }
    }
#pragma unroll
    for (int m = 0; m < 16; m++) {
        int c = c0 + cw + 4 * m;
        g_XG[((size_t)t * G4 + c) * 64 + b] = acc[m] + bih0[c] + bhh0[c];
    }
}

// ---------------------------------------------------------------------------
// Persistent LSTM recurrence on tensor cores. mode 0: layer0 (g_H1f[t] dense),
// mode 1: layer1 (g_H2f parity, planar dump at t=TT-1).
// ---------------------------------------------------------------------------
__global__ void __launch_bounds__(256, 1)
lstm_kernel(const float* __restrict__ Whh, int mode)
{
    extern __shared__ char smem[];
    unsigned*      Bs  = (unsigned*)smem;            // 24576 words (98304 B)
    float*         Cs  = (float*)(smem + 98304);     // 2*64*65 floats (33280 B)
    __nv_bfloat16* Bsh = (__nv_bfloat16*)smem;

    const int tid = threadIdx.x, lane = tid & 31, wid = tid >> 5;
    const int ki = wid >> 2, mi = (wid >> 1) & 1, ni = wid & 1;
    const int nb = blockIdx.x, j0 = nb * 16;

    stage_B(Whh, j0, Bsh, tid);
    __syncthreads();

    const int b = tid & 63, jg = tid >> 6;
    const int r = b & 15, mt = b >> 4;
    const int lane01 = (r & 7) * 4 + 2 * (jg & 1);
    const int reg01  = (r >> 3) + 2 * (jg >> 1);

    float cst[4] = {0.f, 0.f, 0.f, 0.f};

    for (int t = 0; t < TT; t++) {
        const float* xgt = g_XG + (size_t)t * (G4 * 64);
        float xv[4][4];
#pragma unroll
        for (int g = 0; g < 4; g++)
#pragma unroll
            for (int q = 0; q < 4; q++)
                xv[g][q] = __ldcg(xgt + (size_t)(g * 768 + j0 + jg * 4 + q) * 64 + b);

        if (t > 0) {
            const uint4* As = (const uint4*)((mode == 0)
                ? (g_H1f + (size_t)(t - 1) * STEP_WORDS)
                : (g_H2f + (size_t)((t - 1) & 1) * STEP_WORDS));
            gemm_accum_dump(As, Bs, Cs, lane, ki, mi, ni);
        }
        __syncthreads();

        float h[4];
#pragma unroll
        for (int q = 0; q < 4; q++) {
            int jj = jg * 4 + q;
            float gi = xv[0][q], gf = xv[1][q], gg = xv[2][q], go = xv[3][q];
            if (t > 0) {
                gi += Cs[b * 65 + jj]      + Cs[(64 + b) * 65 + jj];
                gf += Cs[b * 65 + 16 + jj] + Cs[(64 + b) * 65 + 16 + jj];
                gg += Cs[b * 65 + 32 + jj] + Cs[(64 + b) * 65 + 32 + jj];
                go += Cs[b * 65 + 48 + jj] + Cs[(64 + b) * 65 + 48 + jj];
            }
            float I = sigmoidf_(gi), F = sigmoidf_(gf);
            float G = tanhf(gg),     O = sigmoidf_(go);
            cst[q] = F * cst[q] + I * G;
            h[q] = O * tanhf(cst[q]);
        }
        unsigned v01 = packbf(h[0], h[1]);
        unsigned v23 = packbf(h[2], h[3]);
        unsigned* dstp = (mode == 0) ? (g_H1f + (size_t)t * STEP_WORDS)
                                     : (g_H2f + (size_t)(t & 1) * STEP_WORDS);
        dstp[((nb * 4 + mt) * 32 + lane01) * 4 + reg01]     = v01;
        dstp[((nb * 4 + mt) * 32 + lane01 + 1) * 4 + reg01] = v23;
        if (mode == 1 && t == TT - 1) {
            float* hp = g_h2pl + (size_t)b * HD + j0 + jg * 4;
            hp[0] = h[0]; hp[1] = h[1]; hp[2] = h[2]; hp[3] = h[3];
        }
        grid_barrier();
    }
}

// ---------------------------------------------------------------------------
// proj1: layer-1 input projection on tensor cores, parallel over t.
// grid (48 nb, 64 tg); each CTA: 4 t's, n=64 gate cols, K=768.
// ---------------------------------------------------------------------------
__global__ void __launch_bounds__(256, 1)
proj1_kernel(const float* __restrict__ Wih1,
             const float* __restrict__ bih1, const float* __restrict__ bhh1)
{
    extern __shared__ char smem[];
    unsigned*      Bs  = (unsigned*)smem;
    float*         Cs  = (float*)(smem + 98304);
    float*         bsS = (float*)(smem + 98304 + 33280);
    __nv_bfloat16* Bsh = (__nv_bfloat16*)smem;

    const int tid = threadIdx.x, lane = tid & 31, wid = tid >> 5;
    const int ki = wid >> 2, mi = (wid >> 1) & 1, ni = wid & 1;
    const int nb = blockIdx.x, j0 = nb * 16;

    stage_B(Wih1, j0, Bsh, tid);
    if (tid < 64) {
        int gate = tid >> 4, jj = tid & 15;
        bsS[tid] = bih1[gate * 768 + j0 + jj] + bhh1[gate * 768 + j0 + jj];
    }
    __syncthreads();

    const int b = tid & 63, jg = tid >> 6;

    for (int tt = 0; tt < 4; tt++) {
        int t = blockIdx.y * 4 + tt;
        const uint4* As = (const uint4*)(g_H1f + (size_t)t * STEP_WORDS);
        gemm_accum_dump(As, Bs, Cs, lane, ki, mi, ni);
        __syncthreads();
        float* xgt = g_XG + (size_t)t * (G4 * 64);
#pragma unroll
        for (int g = 0; g < 4; g++)
#pragma unroll
            for (int q = 0; q < 4; q++) {
                int jj = jg * 4 + q, n = g * 16 + jj;
                float v = Cs[b * 65 + n] + Cs[(64 + b) * 65 + n] + bsS[n];
                xgt[(size_t)(g * 768 + j0 + jj) * 64 + b] = v;
            }
        __syncthreads();
    }
}

// ---------------------------------------------------------------------------
// fc head (fp32, planar h2)
// ---------------------------------------------------------------------------
__global__ void fc_kernel(const float* __restrict__ W1, const float* __restrict__ b1,
                          const float* __restrict__ W2, const float* __restrict__ b2,
                          float* __restrict__ out)
{
    const int b = blockIdx.x;
    const int l = threadIdx.x;

    const float4* h2p = (const float4*)(g_h2pl + (size_t)b * HD);
    const float4* w1p = (const float4*)(W1 + (size_t)l * HD);

    float acc = 0.0f;
#pragma unroll 4
    for (int k4 = 0; k4 < 192; k4++) {
        float4 hv = h2p[k4];
        float4 wv = w1p[k4];
        acc += hv.x * wv.x + hv.y * wv.y + hv.z * wv.z + hv.w * wv.w;
    }
    float z = acc + b1[l];
    float s = z / (1.0f + fabsf(z));
    float p = s * W2[l];

    __shared__ float red[LUD];
    red[l] = p;
    __syncthreads();
    for (int off = LUD / 2; off > 0; off >>= 1) {
        if (l < off) red[l] += red[l + off];
        __syncthreads();
    }
    if (l == 0) out[b] = (red[0] + b2[0]) * 70.0f;
}

// ---------------------------------------------------------------------------
extern "C" void kernel_launch(void* const* d_in, const int* in_sizes, int n_in,
                              void* d_out, int out_size)
{
    const float* x    = (const float*)d_in[0];
    const float* Wih0 = (const float*)d_in[1];
    const float* Whh0 = (const float*)d_in[2];
    const float* bih0 = (const float*)d_in[3];
    const float* bhh0 = (const float*)d_in[4];
    const float* Wih1 = (const float*)d_in[5];
    const float* Whh1 = (const float*)d_in[6];
    const float* bih1 = (const float*)d_in[7];
    const float* bhh1 = (const float*)d_in[8];
    const float* W1   = (const float*)d_in[9];
    const float* b1   = (const float*)d_in[10];
    const float* W2   = (const float*)d_in[11];
    const float* b2   = (const float*)d_in[12];
    float* out = (float*)d_out;

    const int big_smem = 98304 + 33280 + 256;   // 131840 B
    cudaFuncSetAttribute(lstm_kernel,  cudaFuncAttributeMaxDynamicSharedMemorySize, big_smem);
    cudaFuncSetAttribute(proj1_kernel, cudaFuncAttributeMaxDynamicSharedMemorySize, big_smem);

    proj0_kernel<<<dim3(48, 256), 256>>>(x, Wih0, bih0, bhh0);
    lstm_kernel<<<NB, 256, big_smem>>>(Whh0, 0);
    proj1_kernel<<<dim3(48, 64), 256, big_smem>>>(Wih1, bih1, bhh1);
    lstm_kernel<<<NB, 256, big_smem>>>(Whh1, 1);
    fc_kernel<<<BSZ, LUD>>>(W1, b1, W2, b2, out);
}

// round 5
// speedup vs baseline: 6.0810x; 1.9757x over previous
#include <cuda_runtime.h>
#include <cuda_bf16.h>
#include <math.h>

#define BSZ   64
#define TT    256
#define IND   64
#define HD    768
#define G4    3072
#define NB    48          // n-slices (16 gate-cols each)
#define NCTAS 96          // fused persistent grid: 48 layer0 + 48 layer1
#define LUD   256
#define STEP_WORDS 24576  // h frag buffer per step: 48kt*4mt*32lane*4words (98304 B)

__device__ __align__(16) float    g_XG[(size_t)TT * G4 * BSZ];     // [t][c][b] fp32 layer0 gate preacts
__device__ __align__(16) unsigned g_H1f[(size_t)TT * STEP_WORDS];  // h1 bf16 frags, all t
__device__ __align__(16) unsigned g_H2f[2 * STEP_WORDS];           // h2 bf16 frags, parity
__device__ __align__(16) float    g_h2pl[BSZ * HD];                // planar fp32 h2 (last step)
__device__ unsigned long long g_bar = 0;

// ---------------------------------------------------------------------------
// Grid barrier: release-atomic arrival + acquire poll (no full MEMBAR.GPU).
// All cross-CTA payload loads in the loop are __ldcg (L2), so acq/rel suffices.
// ---------------------------------------------------------------------------
__device__ __forceinline__ void grid_barrier()
{
    __syncthreads();
    if (threadIdx.x == 0) {
        unsigned long long old;
        asm volatile("atom.add.release.gpu.u64 %0, [%1], 1;"
                     : "=l"(old) : "l"(&g_bar) : "memory");
        unsigned long long ticket = old + 1ULL;
        unsigned long long need = ((ticket + (NCTAS - 1)) / NCTAS) * NCTAS;
        unsigned long long v;
        for (;;) {
            asm volatile("ld.acquire.gpu.u64 %0, [%1];" : "=l"(v) : "l"(&g_bar) : "memory");
            if (v >= need) break;
            __nanosleep(20);
        }
    }
    __syncthreads();
}

__device__ __forceinline__ float sig_fast(float x)
{
    return __fdividef(1.0f, 1.0f + __expf(-x));
}
__device__ __forceinline__ float tanh_fast(float x)
{
    x = fminf(15.0f, fmaxf(-15.0f, x));
    float e = __expf(2.0f * x);
    return __fdividef(e - 1.0f, e + 1.0f);
}
__device__ __forceinline__ unsigned packbf(float lo, float hi)
{
    __nv_bfloat162 v = __floats2bfloat162_rn(lo, hi);
    return *reinterpret_cast<unsigned*>(&v);
}
__device__ __forceinline__ void mma16816(float* acc, uint4 a, uint2 b)
{
    asm volatile(
        "mma.sync.aligned.m16n8k16.row.col.f32.bf16.bf16.f32 "
        "{%0,%1,%2,%3}, {%4,%5,%6,%7}, {%8,%9}, {%0,%1,%2,%3};"
        : "+f"(acc[0]), "+f"(acc[1]), "+f"(acc[2]), "+f"(acc[3])
        : "r"(a.x), "r"(a.y), "r"(a.z), "r"(a.w), "r"(b.x), "r"(b.y));
}

// Stage one bf16 B-fragment element for weight (n, k) into smem frag layout.
__device__ __forceinline__ void put_Bfrag(__nv_bfloat16* Bsh, int n, int k, float w)
{
    int kt = k >> 4, kr = k & 15, nt = n >> 3, nn = n & 7;
    int lane = nn * 4 + ((kr & 7) >> 1);
    int word = kr >> 3, half = kr & 1;
    Bsh[(((kt * 8 + nt) * 32 + lane) * 2 + word) * 2 + half] = __float2bfloat16(w);
}

// Warp GEMM over NKT k-tiles. As: frag buffer base ([NKT][4][32] uint4, local kt).
// ktg0: global kt offset for B smem indexing. ci: Cs partial row-block.
template<int NKT>
__device__ __forceinline__ void gemm_half(const uint4* __restrict__ As,
                                          const unsigned* __restrict__ Bs,
                                          float* __restrict__ Cs,
                                          int lane, int ci, int mi, int ni, int ktg0)
{
    float acc[2][4][4] = {};
    uint4 abuf[2][12];
#pragma unroll
    for (int kk = 0; kk < 6; kk++) {
        abuf[0][kk * 2 + 0] = __ldcg(As + (kk * 4 + mi * 2 + 0) * 32 + lane);
        abuf[0][kk * 2 + 1] = __ldcg(As + (kk * 4 + mi * 2 + 1) * 32 + lane);
    }
    constexpr int NCH = NKT / 6;
#pragma unroll
    for (int ch = 0; ch < NCH; ch++) {
        if (ch + 1 < NCH) {
#pragma unroll
            for (int kk = 0; kk < 6; kk++) {
                int kt = (ch + 1) * 6 + kk;
                abuf[(ch + 1) & 1][kk * 2 + 0] = __ldcg(As + (kt * 4 + mi * 2 + 0) * 32 + lane);
                abuf[(ch + 1) & 1][kk * 2 + 1] = __ldcg(As + (kt * 4 + mi * 2 + 1) * 32 + lane);
            }
        }
#pragma unroll
        for (int kk = 0; kk < 6; kk++) {
            int kt = ch * 6 + kk;
            uint4 a0 = abuf[ch & 1][kk * 2 + 0];
            uint4 a1 = abuf[ch & 1][kk * 2 + 1];
#pragma unroll
            for (int bn = 0; bn < 4; bn++) {
                int nt = ni * 4 + bn;
                uint2 bb = *(const uint2*)(Bs + (((ktg0 + kt) * 8 + nt) * 32 + lane) * 2);
                mma16816(acc[0][bn], a0, bb);
                mma16816(acc[1][bn], a1, bb);
            }
        }
    }
    int gp = lane >> 2, tig = lane & 3;
#pragma unroll
    for (int am = 0; am < 2; am++)
#pragma unroll
        for (int bn = 0; bn < 4; bn++) {
            int row = mi * 32 + am * 16 + gp;
            int col = ni * 32 + bn * 8 + tig * 2;
            float* cp = Cs + (ci * 64 + row) * 65 + col;
            cp[0] = acc[am][bn][0];
            cp[1] = acc[am][bn][1];
            cp[8 * 65 + 0] = acc[am][bn][2];
            cp[8 * 65 + 1] = acc[am][bn][3];
        }
}

// ---------------------------------------------------------------------------
// proj0 (fp32 precision anchor): g_XG[t][c][b] = (x/1.5)*Wih0^T + bih0 + bhh0
// ---------------------------------------------------------------------------
__global__ void proj0_kernel(const float* __restrict__ x,
                             const float* __restrict__ Wih0,
                             const float* __restrict__ bih0,
                             const float* __restrict__ bhh0)
{
    __shared__ float4 Xs4[64 * 17];
    __shared__ float4 Ws4[64 * 17];
    float* Xs = (float*)Xs4;
    float* Ws = (float*)Ws4;

    const int t   = blockIdx.y;
    const int c0  = blockIdx.x * 64;
    const int tid = threadIdx.x;
    const float inv = 1.0f / 1.5f;

    for (int idx = tid; idx < 64 * 64; idx += 256) {
        int b = idx >> 6, d = idx & 63;
        Xs[b * 68 + d] = x[((b * TT) + t) * IND + d] * inv;
    }
    for (int idx = tid; idx < 64 * 64; idx += 256) {
        int c = idx >> 6, d = idx & 63;
        Ws[c * 68 + d] = Wih0[(c0 + c) * IND + d];
    }
    __syncthreads();

    const int b  = tid & 63;
    const int cw = tid >> 6;

    float acc[16];
#pragma unroll
    for (int m = 0; m < 16; m++) acc[m] = 0.0f;
#pragma unroll
    for (int d4 = 0; d4 < 16; d4++) {
        float4 xv = Xs4[b * 17 + d4];
#pragma unroll
        for (int m = 0; m < 16; m++) {
            float4 wv = Ws4[(cw + 4 * m) * 17 + d4];
            acc[m] += xv.x * wv.x + xv.y * wv.y + xv.z * wv.z + xv.w * wv.w;
        }
    }
#pragma unroll
    for (int m = 0; m < 16; m++) {
        int c = c0 + cw + 4 * m;
        g_XG[((size_t)t * G4 + c) * 64 + b] = acc[m] + bih0[c] + bhh0[c];
    }
}

// ---------------------------------------------------------------------------
// Fused pipelined recurrence: CTAs 0-47 layer0, CTAs 48-95 layer1.
// Barrier step s: L0 computes h1[s] (s<256); L1 computes h2[s-1] (s>=1) from
// h1[s-1]*Wih1^T + h2[s-2]*Whh1^T + b. 257 barriers total.
// ---------------------------------------------------------------------------
__global__ void __launch_bounds__(256, 1)
lstm_fused(const float* __restrict__ Whh0,
           const float* __restrict__ Wih1, const float* __restrict__ Whh1,
           const float* __restrict__ bih1, const float* __restrict__ bhh1)
{
    extern __shared__ char smem[];
    unsigned*      Bs  = (unsigned*)smem;            // L0: 24576 w, L1: 49152 w
    float*         Cs  = (float*)(smem + 196608);    // 2*64*65 f (33280 B)
    float*         bsS = (float*)(smem + 196608 + 33280);
    __nv_bfloat16* Bsh = (__nv_bfloat16*)smem;

    const int tid = threadIdx.x, lane = tid & 31, wid = tid >> 5;
    const int ki = wid >> 2, mi = (wid >> 1) & 1, ni = wid & 1;
    const bool isB = (blockIdx.x >= NB);
    const int nb = isB ? blockIdx.x - NB : blockIdx.x;
    const int j0 = nb * 16;

    if (!isB) {
        for (int idx = tid; idx < 64 * 768; idx += 256) {
            int n = idx / 768, k = idx - n * 768;
            int gate = n >> 4, jj = n & 15;
            put_Bfrag(Bsh, n, k, Whh0[(size_t)(gate * 768 + j0 + jj) * 768 + k]);
        }
    } else {
        for (int idx = tid; idx < 64 * 1536; idx += 256) {
            int n = idx / 1536, k = idx - n * 1536;
            int gate = n >> 4, jj = n & 15;
            float w = (k < 768)
                ? Wih1[(size_t)(gate * 768 + j0 + jj) * 768 + k]
                : Whh1[(size_t)(gate * 768 + j0 + jj) * 768 + (k - 768)];
            put_Bfrag(Bsh, n, k, w);
        }
        if (tid < 64) {
            int gate = tid >> 4, jj = tid & 15;
            bsS[tid] = bih1[gate * 768 + j0 + jj] + bhh1[gate * 768 + j0 + jj];
        }
    }
    __syncthreads();

    const int b = tid & 63, jg = tid >> 6;
    const int r = b & 15, mt = b >> 4;
    const int lane01 = (r & 7) * 4 + 2 * (jg & 1);
    const int reg01  = (r >> 3) + 2 * (jg >> 1);

    float cst[4] = {0.f, 0.f, 0.f, 0.f};

    for (int s = 0; s <= TT; s++) {
        if (!isB) {
            if (s < TT) {
                int t = s;
                const float* xgt = g_XG + (size_t)t * (G4 * 64);
                float xv[4][4];
#pragma unroll
                for (int g = 0; g < 4; g++)
#pragma unroll
                    for (int q = 0; q < 4; q++)
                        xv[g][q] = __ldcg(xgt + (size_t)(g * 768 + j0 + jg * 4 + q) * 64 + b);

                if (t > 0) {
                    const uint4* As = (const uint4*)(g_H1f + (size_t)(t - 1) * STEP_WORDS);
                    gemm_half<24>(As + ki * 3072, Bs, Cs, lane, ki, mi, ni, ki * 24);
                }
                __syncthreads();

                float h[4];
#pragma unroll
                for (int q = 0; q < 4; q++) {
                    int jj = jg * 4 + q;
                    float gi = xv[0][q], gf = xv[1][q], gg = xv[2][q], go = xv[3][q];
                    if (t > 0) {
                        gi += Cs[b * 65 + jj]      + Cs[(64 + b) * 65 + jj];
                        gf += Cs[b * 65 + 16 + jj] + Cs[(64 + b) * 65 + 16 + jj];
                        gg += Cs[b * 65 + 32 + jj] + Cs[(64 + b) * 65 + 32 + jj];
                        go += Cs[b * 65 + 48 + jj] + Cs[(64 + b) * 65 + 48 + jj];
                    }
                    float I = sig_fast(gi), F = sig_fast(gf);
                    float G = tanh_fast(gg), O = sig_fast(go);
                    cst[q] = F * cst[q] + I * G;
                    h[q] = O * tanh_fast(cst[q]);
                }
                unsigned* dstp = g_H1f + (size_t)t * STEP_WORDS;
                dstp[((nb * 4 + mt) * 32 + lane01) * 4 + reg01]     = packbf(h[0], h[1]);
                dstp[((nb * 4 + mt) * 32 + lane01 + 1) * 4 + reg01] = packbf(h[2], h[3]);
            }
        } else {
            if (s >= 1) {
                int t = s - 1;
                if (ki == 0) {
                    const uint4* As = (const uint4*)(g_H1f + (size_t)t * STEP_WORDS);
                    gemm_half<48>(As, Bs, Cs, lane, 0, mi, ni, 0);
                } else if (t > 0) {
                    const uint4* As = (const uint4*)(g_H2f + (size_t)((t - 1) & 1) * STEP_WORDS);
                    gemm_half<48>(As, Bs, Cs, lane, 1, mi, ni, 48);
                }
                __syncthreads();

                float h[4];
#pragma unroll
                for (int q = 0; q < 4; q++) {
                    int jj = jg * 4 + q;
                    float gi = bsS[jj]      + Cs[b * 65 + jj];
                    float gf = bsS[16 + jj] + Cs[b * 65 + 16 + jj];
                    float gg = bsS[32 + jj] + Cs[b * 65 + 32 + jj];
                    float go = bsS[48 + jj] + Cs[b * 65 + 48 + jj];
                    if (t > 0) {
                        gi += Cs[(64 + b) * 65 + jj];
                        gf += Cs[(64 + b) * 65 + 16 + jj];
                        gg += Cs[(64 + b) * 65 + 32 + jj];
                        go += Cs[(64 + b) * 65 + 48 + jj];
                    }
                    float I = sig_fast(gi), F = sig_fast(gf);
                    float G = tanh_fast(gg), O = sig_fast(go);
                    cst[q] = F * cst[q] + I * G;
                    h[q] = O * tanh_fast(cst[q]);
                }
                unsigned* dstp = g_H2f + (size_t)(t & 1) * STEP_WORDS;
                dstp[((nb * 4 + mt) * 32 + lane01) * 4 + reg01]     = packbf(h[0], h[1]);
                dstp[((nb * 4 + mt) * 32 + lane01 + 1) * 4 + reg01] = packbf(h[2], h[3]);
                if (t == TT - 1) {
                    float* hp = g_h2pl + (size_t)b * HD + j0 + jg * 4;
                    hp[0] = h[0]; hp[1] = h[1]; hp[2] = h[2]; hp[3] = h[3];
                }
            }
        }
        grid_barrier();
    }
}

// ---------------------------------------------------------------------------
// fc head (fp32, planar h2)
// ---------------------------------------------------------------------------
__global__ void fc_kernel(const float* __restrict__ W1, const float* __restrict__ b1,
                          const float* __restrict__ W2, const float* __restrict__ b2,
                          float* __restrict__ out)
{
    const int b = blockIdx.x;
    const int l = threadIdx.x;

    const float4* h2p = (const float4*)(g_h2pl + (size_t)b * HD);
    const float4* w1p = (const float4*)(W1 + (size_t)l * HD);

    float acc = 0.0f;
#pragma unroll 4
    for (int k4 = 0; k4 < 192; k4++) {
        float4 hv = h2p[k4];
        float4 wv = w1p[k4];
        acc += hv.x * wv.x + hv.y * wv.y + hv.z * wv.z + hv.w * wv.w;
    }
    float z = acc + b1[l];
    float s = z / (1.0f + fabsf(z));
    float p = s * W2[l];

    __shared__ float red[LUD];
    red[l] = p;
    __syncthreads();
    for (int off = LUD / 2; off > 0; off >>= 1) {
        if (l < off) red[l] += red[l + off];
        __syncthreads();
    }
    if (l == 0) out[b] = (red[0] + b2[0]) * 70.0f;
}

// ---------------------------------------------------------------------------
extern "C" void kernel_launch(void* const* d_in, const int* in_sizes, int n_in,
                              void* d_out, int out_size)
{
    const float* x    = (const float*)d_in[0];
    const float* Wih0 = (const float*)d_in[1];
    const float* Whh0 = (const float*)d_in[2];
    const float* bih0 = (const float*)d_in[3];
    const float* bhh0 = (const float*)d_in[4];
    const float* Wih1 = (const float*)d_in[5];
    const float* Whh1 = (const float*)d_in[6];
    const float* bih1 = (const float*)d_in[7];
    const float* bhh1 = (const float*)d_in[8];
    const float* W1   = (const float*)d_in[9];
    const float* b1   = (const float*)d_in[10];
    const float* W2   = (const float*)d_in[11];
    const float* b2   = (const float*)d_in[12];
    float* out = (float*)d_out;

    const int fused_smem = 196608 + 33280 + 256;   // 230144 B (< 227 KB block max)
    cudaFuncSetAttribute(lstm_fused, cudaFuncAttributeMaxDynamicSharedMemorySize, fused_smem);

    proj0_kernel<<<dim3(48, 256), 256>>>(x, Wih0, bih0, bhh0);
    lstm_fused<<<NCTAS, 256, fused_smem>>>(Whh0, Wih1, Whh1, bih1, bhh1);
    fc_kernel<<<BSZ, LUD>>>(W1, b1, W2, b2, out);
}

// round 6
// speedup vs baseline: 6.2901x; 1.0344x over previous
#include <cuda_runtime.h>
#include <cuda_bf16.h>
#include <math.h>

#define BSZ   64
#define TT    256
#define IND   64
#define HD    768
#define NB    48          // n-slices (16 gate-cols each per layer)
#define NCTAS 96          // 48 layer0 + 48 layer1
#define LUD   256
#define STEP_WORDS 24576  // h frag buffer per step: 48kt*4mt*32lane*4words (98304 B)

// Scratch (static device arrays are the sanctioned workaround)
__device__ __align__(16) unsigned g_Xf[(size_t)TT * 2048];         // x bf16 A-frags: [t][kt*4+mt][lane] uint4
__device__ __align__(16) unsigned g_H1f[(size_t)TT * STEP_WORDS];  // h1 bf16 frags, all t
__device__ __align__(16) unsigned g_H2f[2 * STEP_WORDS];           // h2 bf16 frags, parity
__device__ __align__(16) float    g_h2pl[BSZ * HD];                // planar fp32 h2 (last step)
__device__ unsigned long long g_bar = 0;

// ---------------------------------------------------------------------------
__device__ __forceinline__ void grid_barrier()
{
    __syncthreads();
    if (threadIdx.x == 0) {
        unsigned long long old;
        asm volatile("atom.add.release.gpu.u64 %0, [%1], 1;"
                     : "=l"(old) : "l"(&g_bar) : "memory");
        unsigned long long ticket = old + 1ULL;
        unsigned long long need = ((ticket + (NCTAS - 1)) / NCTAS) * NCTAS;
        unsigned long long v;
        for (;;) {
            asm volatile("ld.acquire.gpu.u64 %0, [%1];" : "=l"(v) : "l"(&g_bar) : "memory");
            if (v >= need) break;
            __nanosleep(20);
        }
    }
    __syncthreads();
}

__device__ __forceinline__ float sig_fast(float x)
{
    return __fdividef(1.0f, 1.0f + __expf(-x));
}
__device__ __forceinline__ float tanh_fast(float x)
{
    x = fminf(15.0f, fmaxf(-15.0f, x));
    float e = __expf(2.0f * x);
    return __fdividef(e - 1.0f, e + 1.0f);
}
__device__ __forceinline__ unsigned packbf(float lo, float hi)
{
    __nv_bfloat162 v = __floats2bfloat162_rn(lo, hi);
    return *reinterpret_cast<unsigned*>(&v);
}
__device__ __forceinline__ void mma16816(float* acc, uint4 a, uint2 b)
{
    asm volatile(
        "mma.sync.aligned.m16n8k16.row.col.f32.bf16.bf16.f32 "
        "{%0,%1,%2,%3}, {%4,%5,%6,%7}, {%8,%9}, {%0,%1,%2,%3};"
        : "+f"(acc[0]), "+f"(acc[1]), "+f"(acc[2]), "+f"(acc[3])
        : "r"(a.x), "r"(a.y), "r"(a.z), "r"(a.w), "r"(b.x), "r"(b.y));
}

// Stage one bf16 B-fragment element for weight (n, k) into smem frag layout.
__device__ __forceinline__ void put_Bfrag(__nv_bfloat16* Bsh, int n, int k, float w)
{
    int kt = k >> 4, kr = k & 15, nt = n >> 3, nn = n & 7;
    int lane = nn * 4 + ((kr & 7) >> 1);
    int word = kr >> 3, half = kr & 1;
    Bsh[(((kt * 8 + nt) * 32 + lane) * 2 + word) * 2 + half] = __float2bfloat16(w);
}

// A-frag load with 2-source split; null src1 -> zeros (t==0 recurrent skip).
__device__ __forceinline__ uint4 loadA(const unsigned* __restrict__ src0,
                                       const unsigned* __restrict__ src1,
                                       int split, int ktg, int mt, int lane)
{
    const unsigned* base;
    int kl;
    if (ktg < split) { base = src0; kl = ktg; }
    else             { base = src1; kl = ktg - split; }
    if (base == nullptr) return make_uint4(0u, 0u, 0u, 0u);
    return __ldcg((const uint4*)base + ((kl * 4 + mt) * 32 + lane));
}

// Warp GEMM: this warp covers ktg in [ki*KT, ki*KT+KT), m-rows mi*32..+31,
// all 64 n-cols. acc[2][8][4]. A via disjoint ldcg, B frags from smem.
template<int KT>
__device__ __forceinline__ void gemm_warp(const unsigned* __restrict__ src0,
                                          const unsigned* __restrict__ src1,
                                          int split,
                                          const unsigned* __restrict__ Bs,
                                          float acc[2][8][4],
                                          int lane, int ki, int mi)
{
    uint4 abuf[4][2];
#pragma unroll
    for (int i = 0; i < 4; i++) {
        int ktg = ki * KT + i;
        abuf[i][0] = loadA(src0, src1, split, ktg, mi * 2 + 0, lane);
        abuf[i][1] = loadA(src0, src1, split, ktg, mi * 2 + 1, lane);
    }
#pragma unroll
    for (int kk = 0; kk < KT; kk++) {
        uint4 a0 = abuf[kk & 3][0];
        uint4 a1 = abuf[kk & 3][1];
        if (kk + 4 < KT) {
            int ktg = ki * KT + kk + 4;
            abuf[kk & 3][0] = loadA(src0, src1, split, ktg, mi * 2 + 0, lane);
            abuf[kk & 3][1] = loadA(src0, src1, split, ktg, mi * 2 + 1, lane);
        }
        int ktg = ki * KT + kk;
        const unsigned* bbase = Bs + ((ktg * 8) * 32 + lane) * 2;
#pragma unroll
        for (int nt = 0; nt < 8; nt++) {
            uint2 bb = *(const uint2*)(bbase + nt * 64);
            mma16816(acc[0][nt], a0, bb);
            mma16816(acc[1][nt], a1, bb);
        }
    }
}

// ---------------------------------------------------------------------------
// xprep: pack x/1.5 into bf16 A-fragments. grid=(TT), 256 thr.
// ---------------------------------------------------------------------------
__global__ void xprep_kernel(const float* __restrict__ x)
{
    const int t = blockIdx.x;
    const int tid = threadIdx.x;
    const float inv = 1.0f / 1.5f;
    for (int idx = tid; idx < 512; idx += 256) {
        int lane = idx & 31;
        int fm = idx >> 5;          // kt*4 + mt
        int kt = fm >> 2, mt = fm & 3;
        int gp = lane >> 2, tig = lane & 3;
        int b0 = mt * 16 + gp, b1 = b0 + 8;
        int k0 = kt * 16 + tig * 2;
        const float* xb0 = x + ((size_t)b0 * TT + t) * IND;
        const float* xb1 = x + ((size_t)b1 * TT + t) * IND;
        uint4 v;
        v.x = packbf(xb0[k0] * inv,     xb0[k0 + 1] * inv);
        v.y = packbf(xb1[k0] * inv,     xb1[k0 + 1] * inv);
        v.z = packbf(xb0[k0 + 8] * inv, xb0[k0 + 9] * inv);
        v.w = packbf(xb1[k0 + 8] * inv, xb1[k0 + 9] * inv);
        ((uint4*)g_Xf)[t * 512 + idx] = v;
    }
}

// ---------------------------------------------------------------------------
// Fused pipelined recurrence. CTAs 0-47 layer0 (K = 64 x + 768 h = 52 kt),
// CTAs 48-95 layer1 (K = 768 h1 + 768 h2 = 96 kt). 257 barrier steps.
// Warps: 8 = (ki 0..3) x (mi 0..1); warp tile m32 x n64 x (KT kt).
// ---------------------------------------------------------------------------
__global__ void __launch_bounds__(256, 1)
lstm_fused(const float* __restrict__ Wih0, const float* __restrict__ Whh0,
           const float* __restrict__ bih0, const float* __restrict__ bhh0,
           const float* __restrict__ Wih1, const float* __restrict__ Whh1,
           const float* __restrict__ bih1, const float* __restrict__ bhh1)
{
    extern __shared__ char smem[];
    unsigned*      Bs  = (unsigned*)smem;                    // up to 49152 uints
    float*         Cs  = (float*)(smem + 196608);            // 64*65 f (16640 B)
    float*         bsS = (float*)(smem + 196608 + 16640);    // 64 f
    __nv_bfloat16* Bsh = (__nv_bfloat16*)smem;

    const int tid = threadIdx.x, lane = tid & 31, wid = tid >> 5;
    const int ki = wid >> 1, mi = wid & 1;
    const bool isB = (blockIdx.x >= NB);
    const int nb = isB ? blockIdx.x - NB : blockIdx.x;
    const int j0 = nb * 16;
    const int gp = lane >> 2, tig = lane & 3;

    // Stage B frags + biases (once)
    if (!isB) {
        for (int idx = tid; idx < 64 * 832; idx += 256) {
            int n = idx / 832, k = idx - n * 832;
            int gate = n >> 4, jj = n & 15;
            float w = (k < 64)
                ? Wih0[(size_t)(gate * 768 + j0 + jj) * 64 + k]
                : Whh0[(size_t)(gate * 768 + j0 + jj) * 768 + (k - 64)];
            put_Bfrag(Bsh, n, k, w);
        }
        if (tid < 64) {
            int g = tid >> 4, jj = tid & 15;
            bsS[tid] = bih0[g * 768 + j0 + jj] + bhh0[g * 768 + j0 + jj];
        }
    } else {
        for (int idx = tid; idx < 64 * 1536; idx += 256) {
            int n = idx / 1536, k = idx - n * 1536;
            int gate = n >> 4, jj = n & 15;
            float w = (k < 768)
                ? Wih1[(size_t)(gate * 768 + j0 + jj) * 768 + k]
                : Whh1[(size_t)(gate * 768 + j0 + jj) * 768 + (k - 768)];
            put_Bfrag(Bsh, n, k, w);
        }
        if (tid < 64) {
            int g = tid >> 4, jj = tid & 15;
            bsS[tid] = bih1[g * 768 + j0 + jj] + bhh1[g * 768 + j0 + jj];
        }
    }
    __syncthreads();

    const int b = tid & 63, jg = tid >> 6;
    const int r = b & 15, mt = b >> 4;
    const int lane01 = (r & 7) * 4 + 2 * (jg & 1);
    const int reg01  = (r >> 3) + 2 * (jg >> 1);

    float cst[4] = {0.f, 0.f, 0.f, 0.f};

    for (int s = 0; s <= TT; s++) {
        const bool active = isB ? (s >= 1) : (s < TT);
        if (active) {
            const int t = isB ? s - 1 : s;

            float acc[2][8][4];
#pragma unroll
            for (int am = 0; am < 2; am++)
#pragma unroll
                for (int nt = 0; nt < 8; nt++)
#pragma unroll
                    for (int e = 0; e < 4; e++) acc[am][nt][e] = 0.f;

            if (!isB) {
                const unsigned* src0 = g_Xf + (size_t)t * 2048;
                const unsigned* src1 = (t > 0) ? g_H1f + (size_t)(t - 1) * STEP_WORDS : nullptr;
                gemm_warp<13>(src0, src1, 4, Bs, acc, lane, ki, mi);
            } else {
                const unsigned* src0 = g_H1f + (size_t)t * STEP_WORDS;
                const unsigned* src1 = (t > 0) ? g_H2f + (size_t)((t - 1) & 1) * STEP_WORDS : nullptr;
                gemm_warp<24>(src0, src1, 48, Bs, acc, lane, ki, mi);
            }

            // Combine the 4 k-split partials in Cs via 4 sequential phases
#pragma unroll
            for (int p = 0; p < 4; p++) {
                if (ki == p) {
#pragma unroll
                    for (int am = 0; am < 2; am++)
#pragma unroll
                        for (int nt = 0; nt < 8; nt++) {
                            int row = mi * 32 + am * 16 + gp;
                            int col = nt * 8 + tig * 2;
                            float* c0 = Cs + row * 65 + col;
                            float* c1 = Cs + (row + 8) * 65 + col;
                            if (p == 0) {
                                c0[0] = acc[am][nt][0];
                                c0[1] = acc[am][nt][1];
                                c1[0] = acc[am][nt][2];
                                c1[1] = acc[am][nt][3];
                            } else {
                                c0[0] += acc[am][nt][0];
                                c0[1] += acc[am][nt][1];
                                c1[0] += acc[am][nt][2];
                                c1[1] += acc[am][nt][3];
                            }
                        }
                }
                __syncthreads();
            }

            // Epilogue: gates -> h ; write h frags
            float h[4];
#pragma unroll
            for (int q = 0; q < 4; q++) {
                int jj = jg * 4 + q;
                float gi = bsS[jj]      + Cs[b * 65 + jj];
                float gf = bsS[16 + jj] + Cs[b * 65 + 16 + jj];
                float gg = bsS[32 + jj] + Cs[b * 65 + 32 + jj];
                float go = bsS[48 + jj] + Cs[b * 65 + 48 + jj];
                float I = sig_fast(gi), F = sig_fast(gf);
                float G = tanh_fast(gg), O = sig_fast(go);
                cst[q] = F * cst[q] + I * G;
                h[q] = O * tanh_fast(cst[q]);
            }
            unsigned* dstp = isB ? (g_H2f + (size_t)(t & 1) * STEP_WORDS)
                                 : (g_H1f + (size_t)t * STEP_WORDS);
            dstp[((nb * 4 + mt) * 32 + lane01) * 4 + reg01]     = packbf(h[0], h[1]);
            dstp[((nb * 4 + mt) * 32 + lane01 + 1) * 4 + reg01] = packbf(h[2], h[3]);
            if (isB && t == TT - 1) {
                float* hp = g_h2pl + (size_t)b * HD + j0 + jg * 4;
                hp[0] = h[0]; hp[1] = h[1]; hp[2] = h[2]; hp[3] = h[3];
            }
        }
        grid_barrier();
    }
}

// ---------------------------------------------------------------------------
// fc head (fp32, planar h2)
// ---------------------------------------------------------------------------
__global__ void fc_kernel(const float* __restrict__ W1, const float* __restrict__ b1,
                          const float* __restrict__ W2, const float* __restrict__ b2,
                          float* __restrict__ out)
{
    const int b = blockIdx.x;
    const int l = threadIdx.x;

    const float4* h2p = (const float4*)(g_h2pl + (size_t)b * HD);
    const float4* w1p = (const float4*)(W1 + (size_t)l * HD);

    float acc = 0.0f;
#pragma unroll 4
    for (int k4 = 0; k4 < 192; k4++) {
        float4 hv = h2p[k4];
        float4 wv = w1p[k4];
        acc += hv.x * wv.x + hv.y * wv.y + hv.z * wv.z + hv.w * wv.w;
    }
    float z = acc + b1[l];
    float s = z / (1.0f + fabsf(z));
    float p = s * W2[l];

    __shared__ float red[LUD];
    red[l] = p;
    __syncthreads();
    for (int off = LUD / 2; off > 0; off >>= 1) {
        if (l < off) red[l] += red[l + off];
        __syncthreads();
    }
    if (l == 0) out[b] = (red[0] + b2[0]) * 70.0f;
}

// ---------------------------------------------------------------------------
extern "C" void kernel_launch(void* const* d_in, const int* in_sizes, int n_in,
                              void* d_out, int out_size)
{
    const float* x    = (const float*)d_in[0];
    const float* Wih0 = (const float*)d_in[1];
    const float* Whh0 = (const float*)d_in[2];
    const float* bih0 = (const float*)d_in[3];
    const float* bhh0 = (const float*)d_in[4];
    const float* Wih1 = (const float*)d_in[5];
    const float* Whh1 = (const float*)d_in[6];
    const float* bih1 = (const float*)d_in[7];
    const float* bhh1 = (const float*)d_in[8];
    const float* W1   = (const float*)d_in[9];
    const float* b1   = (const float*)d_in[10];
    const float* W2   = (const float*)d_in[11];
    const float* b2   = (const float*)d_in[12];
    float* out = (float*)d_out;

    const int fused_smem = 196608 + 16640 + 256;   // 213504 B
    cudaFuncSetAttribute(lstm_fused, cudaFuncAttributeMaxDynamicSharedMemorySize, fused_smem);

    xprep_kernel<<<TT, 256>>>(x);
    lstm_fused<<<NCTAS, 256, fused_smem>>>(Wih0, Whh0, bih0, bhh0,
                                           Wih1, Whh1, bih1, bhh1);
    fc_kernel<<<BSZ, LUD>>>(W1, b1, W2, b2, out);
}